// round 5
// baseline (speedup 1.0000x reference)
#include <cuda_runtime.h>
#include <math.h>
#include <stdint.h>

// Problem-size maxima (fixed by the dataset: N=100000, E=1600000, F=H=128, OUT=40)
#define NMAX 100000
#define EMAX 1600000
#define FDIM 128

// ---------------- scratch (static device globals; no allocation) ----------------
__device__ __align__(16) float g_bufG[(size_t)NMAX * FDIM];   // g = (A@W)*dinv (layer 1/2)
__device__ __align__(16) float g_bufO[(size_t)NMAX * FDIM];   // out1, then s = out2+out1
__device__ float g_dinv[NMAX];
__device__ int   g_cnt[NMAX];
__device__ int   g_rowstart[NMAX + 1];
__device__ int   g_cursor[NMAX];
__device__ int   g_csrc[EMAX];

// ---------------- CSR build ----------------
__global__ void zero_cnt_kernel(int n) {
    int i = blockIdx.x * blockDim.x + threadIdx.x;
    if (i < n) g_cnt[i] = 0;
}

__global__ void count_kernel(const int* __restrict__ dst, int e) {
    int i = blockIdx.x * blockDim.x + threadIdx.x;
    if (i < e) atomicAdd(&g_cnt[dst[i]], 1);
}

// Single-block exclusive scan over counts -> rowstart/cursor; also dinv = rsqrt(cnt+1).
__global__ void scan_kernel(int n, int e_total) {
    __shared__ int sums[1024];
    int t = threadIdx.x;
    int chunk = (n + 1023) >> 10;
    int lo = t * chunk;
    int hi = lo + chunk; if (hi > n) hi = n;
    int s = 0;
    for (int i = lo; i < hi; i++) s += g_cnt[i];
    sums[t] = s;
    __syncthreads();
    // Hillis-Steele inclusive scan
    for (int off = 1; off < 1024; off <<= 1) {
        int v = (t >= off) ? sums[t - off] : 0;
        __syncthreads();
        sums[t] += v;
        __syncthreads();
    }
    int prefix = (t == 0) ? 0 : sums[t - 1];
    for (int i = lo; i < hi; i++) {
        int c = g_cnt[i];
        g_rowstart[i] = prefix;
        g_cursor[i]   = prefix;
        g_dinv[i]     = rsqrtf((float)(c + 1));   // +1 self loop
        prefix += c;
    }
    if (t == 1023) g_rowstart[n] = e_total;
}

__global__ void place_kernel(const int* __restrict__ src, const int* __restrict__ dst, int e) {
    int i = blockIdx.x * blockDim.x + threadIdx.x;
    if (i < e) {
        int d = dst[i];
        int p = atomicAdd(&g_cursor[d], 1);
        g_csrc[p] = src[i];
    }
}

// ---------------- GEMM: C[row] = (A @ W) * dinv[row];  A:[n,128], W:[128,128] ----------------
// Tile: 64 rows x 128 cols, BK=32, 256 threads, 8x4 micro-tile per thread.
__global__ __launch_bounds__(256) void gemm_nk128(const float* __restrict__ A,
                                                  const float* __restrict__ W,
                                                  float* __restrict__ C, int n) {
    __shared__ float As[64][32];
    __shared__ float Bs[32][128];
    int m0 = blockIdx.x * 64;
    int t = threadIdx.x;
    int colq = t & 31;   // 4 cols: colq*4 .. +3
    int rg   = t >> 5;   // 8 rows: rg*8 .. +7
    float acc[8][4];
#pragma unroll
    for (int r = 0; r < 8; r++)
#pragma unroll
        for (int c = 0; c < 4; c++) acc[r][c] = 0.0f;

    for (int k0 = 0; k0 < 128; k0 += 32) {
        // load A tile (2048 floats)
#pragma unroll
        for (int j = 0; j < 2; j++) {
            int flat = t * 8 + j * 4;
            int row = flat >> 5, kk = flat & 31;
            float4 v = make_float4(0.f, 0.f, 0.f, 0.f);
            if (m0 + row < n)
                v = *(const float4*)(A + (size_t)(m0 + row) * 128 + k0 + kk);
            *(float4*)&As[row][kk] = v;
        }
        // load W tile (4096 floats)
#pragma unroll
        for (int j = 0; j < 4; j++) {
            int flat = t * 16 + j * 4;
            int kr = flat >> 7, cc = flat & 127;
            *(float4*)&Bs[kr][cc] = *(const float4*)(W + (size_t)(k0 + kr) * 128 + cc);
        }
        __syncthreads();
#pragma unroll 8
        for (int k = 0; k < 32; k++) {
            float4 b = *(float4*)&Bs[k][colq * 4];
#pragma unroll
            for (int r = 0; r < 8; r++) {
                float a = As[rg * 8 + r][k];
                acc[r][0] += a * b.x;
                acc[r][1] += a * b.y;
                acc[r][2] += a * b.z;
                acc[r][3] += a * b.w;
            }
        }
        __syncthreads();
    }
#pragma unroll
    for (int r = 0; r < 8; r++) {
        int row = m0 + rg * 8 + r;
        if (row < n) {
            float s = g_dinv[row];
            float4 o = make_float4(acc[r][0] * s, acc[r][1] * s, acc[r][2] * s, acc[r][3] * s);
            *(float4*)(C + (size_t)row * 128 + colq * 4) = o;
        }
    }
}

// ---------------- Aggregation: warp per node (pull / gather) ----------------
// O[i] = relu( dinv[i] * ( sum_{j in nbr(i)} G[j] + G[i] ) + bias )  [+ resid[i]]
__global__ __launch_bounds__(256) void aggregate_kernel(const float* __restrict__ G,
                                                        const float* __restrict__ bias,
                                                        float* O, const float* resid,
                                                        int has_resid, int n) {
    int warp = (blockIdx.x * blockDim.x + threadIdx.x) >> 5;
    int lane = threadIdx.x & 31;
    if (warp >= n) return;
    int s = g_rowstart[warp];
    int e = g_rowstart[warp + 1];
    const float4* G4 = (const float4*)G;
    size_t self = (size_t)warp * 32 + lane;
    float4 acc = G4[self];                       // self loop
    for (int i = s; i < e; i++) {
        int j = g_csrc[i];
        float4 v = G4[(size_t)j * 32 + lane];
        acc.x += v.x; acc.y += v.y; acc.z += v.z; acc.w += v.w;
    }
    float d = g_dinv[warp];
    float4 b = ((const float4*)bias)[lane];
    acc.x = fmaxf(fmaf(acc.x, d, b.x), 0.f);
    acc.y = fmaxf(fmaf(acc.y, d, b.y), 0.f);
    acc.z = fmaxf(fmaf(acc.z, d, b.z), 0.f);
    acc.w = fmaxf(fmaf(acc.w, d, b.w), 0.f);
    if (has_resid) {
        float4 r = ((const float4*)resid)[self];
        acc.x += r.x; acc.y += r.y; acc.z += r.z; acc.w += r.w;
    }
    ((float4*)O)[self] = acc;
}

// ---------------- Output GEMM: out = S @ Wc + bc;  S:[n,128], Wc:[128,40] ----------------
// Tile: 128 rows, 256 threads; thread = 4 rows x 5 cols (c0, c0+8, ..., c0+32).
__global__ __launch_bounds__(256) void gemm_out_kernel(const float* __restrict__ S,
                                                       const float* __restrict__ Wc,
                                                       const float* __restrict__ bc,
                                                       float* __restrict__ out, int n) {
    __shared__ float Ws[128][40];
    __shared__ float Ss[128][33];   // pad 33 -> conflict-free column reads
    __shared__ float bs[40];
    int t = threadIdx.x;
    int m0 = blockIdx.x * 128;
    for (int i = t; i < 128 * 40; i += 256) Ws[i / 40][i % 40] = Wc[i];
    if (t < 40) bs[t] = bc[t];

    int c0 = t & 7;     // 5 cols: c0 + 8*j
    int rq = t >> 3;    // 4 rows: rq*4 .. +3
    float acc[4][5];
#pragma unroll
    for (int r = 0; r < 4; r++)
#pragma unroll
        for (int j = 0; j < 5; j++) acc[r][j] = 0.0f;

    for (int k0 = 0; k0 < 128; k0 += 32) {
        __syncthreads();
        // stage S tile [128 rows x 32 k]
#pragma unroll
        for (int j = 0; j < 4; j++) {
            int flat = t * 16 + j * 4;
            int row = flat >> 5, kk = flat & 31;
            float4 v = make_float4(0.f, 0.f, 0.f, 0.f);
            if (m0 + row < n)
                v = *(const float4*)(S + (size_t)(m0 + row) * 128 + k0 + kk);
            Ss[row][kk + 0] = v.x;
            Ss[row][kk + 1] = v.y;
            Ss[row][kk + 2] = v.z;
            Ss[row][kk + 3] = v.w;
        }
        __syncthreads();
#pragma unroll 8
        for (int k = 0; k < 32; k++) {
            float w0 = Ws[k0 + k][c0];
            float w1 = Ws[k0 + k][c0 + 8];
            float w2 = Ws[k0 + k][c0 + 16];
            float w3 = Ws[k0 + k][c0 + 24];
            float w4 = Ws[k0 + k][c0 + 32];
#pragma unroll
            for (int r = 0; r < 4; r++) {
                float a = Ss[rq * 4 + r][k];
                acc[r][0] += a * w0;
                acc[r][1] += a * w1;
                acc[r][2] += a * w2;
                acc[r][3] += a * w3;
                acc[r][4] += a * w4;
            }
        }
    }
#pragma unroll
    for (int r = 0; r < 4; r++) {
        int row = m0 + rq * 4 + r;
        if (row < n) {
#pragma unroll
            for (int j = 0; j < 5; j++)
                out[(size_t)row * 40 + c0 + 8 * j] = acc[r][j] + bs[c0 + 8 * j];
        }
    }
}

// ---------------- launch ----------------
extern "C" void kernel_launch(void* const* d_in, const int* in_sizes, int n_in,
                              void* d_out, int out_size) {
    const float* x  = (const float*)d_in[0];
    const float* W1 = (const float*)d_in[1];
    const float* b1 = (const float*)d_in[2];
    const float* W2 = (const float*)d_in[3];
    const float* b2 = (const float*)d_in[4];
    const float* Wc = (const float*)d_in[5];
    const float* bc = (const float*)d_in[6];
    const int*   ei = (const int*)d_in[7];

    int N = in_sizes[0] / FDIM;
    int E = in_sizes[7] / 2;
    if (N > NMAX) N = NMAX;
    if (E > EMAX) E = EMAX;
    const int* src = ei;
    const int* dst = ei + E;

    float *G, *O;
    cudaGetSymbolAddress((void**)&G, g_bufG);
    cudaGetSymbolAddress((void**)&O, g_bufO);

    // CSR build (by dst) + degrees
    zero_cnt_kernel<<<(N + 255) / 256, 256>>>(N);
    count_kernel<<<(E + 255) / 256, 256>>>(dst, E);
    scan_kernel<<<1, 1024>>>(N, E);
    place_kernel<<<(E + 255) / 256, 256>>>(src, dst, E);

    int gemm_grid = (N + 63) / 64;
    int agg_grid  = (N * 32 + 255) / 256;

    // Layer 1: g = (x@W1)*dinv ; out1 = relu(dinv*(agg+self)+b1)
    gemm_nk128<<<gemm_grid, 256>>>(x, W1, G, N);
    aggregate_kernel<<<agg_grid, 256>>>(G, b1, O, nullptr, 0, N);

    // Layer 2: g2 = (out1@W2)*dinv ; s = relu(dinv*(agg+self)+b2) + out1   (in place)
    gemm_nk128<<<gemm_grid, 256>>>(O, W2, G, N);
    aggregate_kernel<<<agg_grid, 256>>>(G, b2, O, O, 1, N);

    // Output: out = s @ Wc + bc
    gemm_out_kernel<<<(N + 127) / 128, 256>>>(O, Wc, bc, (float*)d_out, N);
}